// round 15
// baseline (speedup 1.0000x reference)
#include <cuda_runtime.h>
#include <cuda_bf16.h>
#include <cstdint>

// Problem: B=32, T=32, L=196, S=512, D=512
// Math reduction: softmax is shift-invariant => attention independent of h,t.
//   attn[b,:]  = softmax_l( x_static[b] @ (W1@V) )
//   ctx[b,:]   = attn[b,:] @ x_static[b]
//   out[b,t,:] = concat(x[b,t,:], ctx[b,:]) @ W3 + b3   (K=1024 TF32 MMA GEMM)
//
// GEMM operands are stored in *mma fragment order* in global memory so the
// mainloop does LDS.128/LDS.64 instead of scalar LDS.32, and the ctx region
// needs no special-casing. 3-stage cp.async pipeline.

#define D_ 512
#define S_ 512
#define L_ 196
#define B_ 32
#define T_ 32
#define KTOT 1024
#define M_ 1024
#define LCH 7
#define LPC 28
#define NT 32            // K tiles of 32

__device__ float g_w1v[S_];
__device__ float g_scores[B_ * L_];
__device__ __align__(16) float g_ctxpart[LCH][B_][S_];
__device__ unsigned int g_ctx_cnt[B_];
// A fragments: [mfrag 0..63][k8 0..127][lane 0..31] -> uint4 {a0,a1,a2,a3}
__device__ __align__(16) uint4 g_Afrag[64 * 128 * 32];
// B fragments: [k8 0..127][nfrag 0..63][lane 0..31] -> uint2 {b0,b1}
__device__ __align__(16) uint2 g_Bfrag[128 * 64 * 32];

__device__ __forceinline__ uint32_t f2tf32(float f) {
    uint32_t u;
    asm("cvt.rna.tf32.f32 %0, %1;" : "=r"(u) : "f"(f));
    return u;
}
__device__ __forceinline__ void cp_async16(void* smem, const void* gptr) {
    uint32_t sa = (uint32_t)__cvta_generic_to_shared(smem);
    asm volatile("cp.async.cg.shared.global [%0], [%1], 16;\n" ::"r"(sa), "l"(gptr));
}
__device__ __forceinline__ void cp_commit() {
    asm volatile("cp.async.commit_group;\n");
}
template <int N>
__device__ __forceinline__ void cp_wait() {
    asm volatile("cp.async.wait_group %0;\n" ::"n"(N));
}

// ---------------------------------------------------------------------------
// Kernel 1 (fused prep): x -> A fragments (k8 0..63), W3 -> B fragments,
// w1v = W1@V, counter reset. 256 blocks x 256 threads.
// ---------------------------------------------------------------------------
__global__ __launch_bounds__(256) void prep_fused(const float* __restrict__ x,
                                                  const float* __restrict__ W3,
                                                  const float* __restrict__ W1,
                                                  const float* __restrict__ V) {
    int gtid = blockIdx.x * 256 + threadIdx.x;  // 0..65535

    if (blockIdx.x == 0 && threadIdx.x < B_) g_ctx_cnt[threadIdx.x] = 0u;

    // A fragments from x: 64 mf * 64 kb * 32 lanes = 131072 entries, 2/thread
#pragma unroll
    for (int it = 0; it < 2; it++) {
        int e = gtid + it * 65536;
        int mf = e >> 11;
        int rem = e & 2047;
        int kb = rem >> 5;
        int l = rem & 31;
        int r = l >> 2, c = l & 3;
        const float* xa = x + (size_t)(mf * 16 + r) * D_ + kb * 8 + c;
        uint4 u;
        u.x = f2tf32(xa[0]);
        u.y = f2tf32(xa[8 * D_]);
        u.z = f2tf32(xa[4]);
        u.w = f2tf32(xa[8 * D_ + 4]);
        g_Afrag[((size_t)mf * 128 + kb) * 32 + l] = u;
    }

    // B fragments from W3: 128 kb * 64 nf * 32 lanes = 262144 entries, 4/thread
#pragma unroll
    for (int it = 0; it < 4; it++) {
        int e = gtid + it * 65536;
        int kb = e >> 11;
        int rem = e & 2047;
        int nf = rem >> 5;
        int l = rem & 31;
        int r = l >> 2, c = l & 3;
        const float* wb = W3 + (size_t)(kb * 8 + c) * D_ + nf * 8 + r;
        uint2 u;
        u.x = f2tf32(wb[0]);
        u.y = f2tf32(wb[4 * D_]);
        g_Bfrag[((size_t)kb * 64 + nf) * 32 + l] = u;
    }

    // w1v: first 512 warps, warp per row
    int gwarp = gtid >> 5;
    int lane = threadIdx.x & 31;
    if (gwarp < S_) {
        const float4* row = (const float4*)(W1 + (size_t)gwarp * D_);
        const float4* v4 = (const float4*)V;
        float acc = 0.0f;
#pragma unroll
        for (int i = 0; i < 4; i++) {
            int idx = lane + i * 32;
            float4 a = row[idx];
            float4 b = v4[idx];
            acc += a.x * b.x + a.y * b.y + a.z * b.z + a.w * b.w;
        }
#pragma unroll
        for (int o = 16; o; o >>= 1) acc += __shfl_xor_sync(0xffffffffu, acc, o);
        if (lane == 0) g_w1v[gwarp] = acc;
    }
}

// ---------------------------------------------------------------------------
// Kernel 2: scores[b,l] = dot(x_static[b,l,:], w1v). grid (7, 32), warp/row.
// ---------------------------------------------------------------------------
__global__ __launch_bounds__(256) void scores_kernel(const float* __restrict__ xs) {
    int b = blockIdx.y;
    int l0 = blockIdx.x * LPC;
    __shared__ __align__(16) float sw1v[S_];
    int tid = threadIdx.x;
    if (tid < S_ / 4) ((float4*)sw1v)[tid] = ((const float4*)g_w1v)[tid];
    __syncthreads();

    int warp = tid >> 5, lane = tid & 31;
    const float* X = xs + (size_t)b * L_ * S_;
    for (int r = warp; r < LPC; r += 8) {
        int l = l0 + r;
        const float4* row = (const float4*)(X + (size_t)l * S_);
        const float4* w4 = (const float4*)sw1v;
        float acc = 0.0f;
#pragma unroll
        for (int i = 0; i < 4; i++) {
            int idx = lane + i * 32;
            float4 a = row[idx];
            float4 w = w4[idx];
            acc += a.x * w.x + a.y * w.y + a.z * w.z + a.w * w.w;
        }
#pragma unroll
        for (int o = 16; o; o >>= 1) acc += __shfl_xor_sync(0xffffffffu, acc, o);
        if (lane == 0) g_scores[b * L_ + l] = acc;
    }
}

// ---------------------------------------------------------------------------
// Kernel 3 (fused): softmax recompute + ctx partial + last-block reduce,
// which writes the ctx A-fragments (k8 64..127, broadcast rows).
// grid (7 l-chunks, 32 b), block 128.
// ---------------------------------------------------------------------------
__global__ __launch_bounds__(128) void ctx_fused(const float* __restrict__ xs) {
    int b = blockIdx.y;
    int lc = blockIdx.x;
    int l0 = lc * LPC;
    int tid = threadIdx.x;
    int warp = tid >> 5, lane = tid & 31;

    __shared__ __align__(16) float sctx[S_];
    __shared__ __align__(16) float ssc[256];
    __shared__ float red[4];
    __shared__ float s_max, s_sum;
    __shared__ unsigned int s_last;
    __shared__ float sattn[LPC];

    float v0 = g_scores[b * L_ + tid];
    float v1 = (tid + 128 < L_) ? g_scores[b * L_ + tid + 128] : -1e30f;
    ssc[tid] = v0;
    ssc[tid + 128] = v1;

    float m = fmaxf(v0, v1);
#pragma unroll
    for (int o = 16; o; o >>= 1) m = fmaxf(m, __shfl_xor_sync(0xffffffffu, m, o));
    if (lane == 0) red[warp] = m;
    __syncthreads();
    if (tid == 0) s_max = fmaxf(fmaxf(red[0], red[1]), fmaxf(red[2], red[3]));
    __syncthreads();
    float mx = s_max;

    float e0 = __expf(v0 - mx);
    float e1 = (tid + 128 < L_) ? __expf(v1 - mx) : 0.0f;
    float ps = e0 + e1;
#pragma unroll
    for (int o = 16; o; o >>= 1) ps += __shfl_xor_sync(0xffffffffu, ps, o);
    if (lane == 0) red[warp] = ps;
    __syncthreads();
    if (tid == 0) s_sum = red[0] + red[1] + red[2] + red[3];
    __syncthreads();
    float inv = 1.0f / s_sum;

    if (tid < LPC) sattn[tid] = __expf(ssc[l0 + tid] - mx) * inv;
    __syncthreads();

    const float4* Xp = (const float4*)(xs + (size_t)b * L_ * S_ + (size_t)l0 * S_) + tid;
    float4 acc = {0.0f, 0.0f, 0.0f, 0.0f};
#pragma unroll 4
    for (int l = 0; l < LPC; l++) {
        float w = sattn[l];
        float4 v = Xp[l * (S_ / 4)];
        acc.x += w * v.x;
        acc.y += w * v.y;
        acc.z += w * v.z;
        acc.w += w * v.w;
    }
    *(float4*)&g_ctxpart[lc][b][tid * 4] = acc;

    __threadfence();
    __syncthreads();
    if (tid == 0) s_last = atomicAdd(&g_ctx_cnt[b], 1u);
    __syncthreads();
    if (s_last == LCH - 1) {   // uniform branch (s_last is shared)
        __threadfence();
        float4 t = {0.0f, 0.0f, 0.0f, 0.0f};
#pragma unroll
        for (int k = 0; k < LCH; k++) {
            float4 p = *(const float4*)&g_ctxpart[k][b][tid * 4];
            t.x += p.x;
            t.y += p.y;
            t.z += p.z;
            t.w += p.w;
        }
        *(float4*)&sctx[tid * 4] = t;
        __syncthreads();
        // write ctx A-fragments: mfrags 2b, 2b+1; k8 64..127; rows broadcast.
        // entries = 2 * 64 * 32 = 4096 -> 32 per thread.
#pragma unroll
        for (int i = 0; i < 32; i++) {
            int e = tid + i * 128;       // 0..4095
            int mfs = e >> 11;           // 0/1
            int rem = e & 2047;
            int kb = 64 + (rem >> 5);
            int l = rem & 31;
            int c = l & 3;
            int k8 = (kb - 64) * 8;
            uint32_t tl = f2tf32(sctx[k8 + c]);
            uint32_t th = f2tf32(sctx[k8 + c + 4]);
            uint4 u;
            u.x = tl;
            u.y = tl;
            u.z = th;
            u.w = th;
            g_Afrag[((size_t)(2 * b + mfs) * 128 + kb) * 32 + l] = u;
        }
    }
}

// ---------------------------------------------------------------------------
// Kernel 4: TF32 MMA GEMM on fragment-ordered operands.
// M=1024, N=512, K=1024. BM=64, BN=64, BK=32, grid (8,16), 256 threads,
// 8 warps: m_sel = w&1 (2 mfrags), n_sel = w>>1 (2 nfrags). 3-stage cp.async.
// ---------------------------------------------------------------------------
__global__ __launch_bounds__(256) void gemm_tc(const float* __restrict__ b3,
                                               float* __restrict__ out) {
    __shared__ __align__(16) uint4 As[3][4][4][32];  // [stage][mf][kk8][lane]
    __shared__ __align__(16) uint2 Bs[3][4][8][32];  // [stage][kk8][nf][lane]

    int tid = threadIdx.x;
    int w = tid >> 5, lane = tid & 31;
    int bx = blockIdx.x, by = blockIdx.y;
    int m_sel = w & 1;
    int n_sel = w >> 1;   // 0..3

    float d[2][2][4];
#pragma unroll
    for (int f = 0; f < 2; f++)
#pragma unroll
        for (int g = 0; g < 2; g++)
#pragma unroll
            for (int i = 0; i < 4; i++) d[f][g][i] = 0.0f;

    auto issue_tile = [&](int t) {
        int st = t % 3;
        int kb0 = t * 4;
        // A: 512 uint4 chunks, 2 per thread
#pragma unroll
        for (int it = 0; it < 2; it++) {
            int s = tid + it * 256;
            int mf = s >> 7;
            int kk8 = (s >> 5) & 3;
            int l = s & 31;
            cp_async16(&As[st][mf][kk8][l],
                       &g_Afrag[((size_t)(by * 4 + mf) * 128 + kb0 + kk8) * 32 + l]);
        }
        // B: 512 x 16B chunks (uint2 pairs), 2 per thread
#pragma unroll
        for (int it = 0; it < 2; it++) {
            int s = tid + it * 256;
            int kk8 = s >> 7;
            int nf = (s >> 4) & 7;
            int lp = s & 15;
            cp_async16(&Bs[st][kk8][nf][lp * 2],
                       &g_Bfrag[((size_t)(kb0 + kk8) * 64 + bx * 8 + nf) * 32 + lp * 2]);
        }
        cp_commit();
    };

    issue_tile(0);
    issue_tile(1);

    for (int t = 0; t < NT; t++) {
        if (t + 2 < NT) {
            issue_tile(t + 2);
            cp_wait<2>();
        } else if (t + 1 < NT) {
            cp_wait<1>();
        } else {
            cp_wait<0>();
        }
        __syncthreads();
        int st = t % 3;

#pragma unroll
        for (int kk8 = 0; kk8 < 4; kk8++) {
            uint4 a0 = As[st][m_sel * 2 + 0][kk8][lane];
            uint4 a1 = As[st][m_sel * 2 + 1][kk8][lane];
            uint2 b0 = Bs[st][kk8][n_sel * 2 + 0][lane];
            uint2 b1 = Bs[st][kk8][n_sel * 2 + 1][lane];
#define MMA_(acc, av, bv)                                                        \
    asm volatile(                                                                \
        "mma.sync.aligned.m16n8k8.row.col.f32.tf32.tf32.f32 "                    \
        "{%0,%1,%2,%3}, {%4,%5,%6,%7}, {%8,%9}, {%0,%1,%2,%3};\n"                \
        : "+f"(acc[0]), "+f"(acc[1]), "+f"(acc[2]), "+f"(acc[3])                 \
        : "r"(av.x), "r"(av.y), "r"(av.z), "r"(av.w), "r"(bv.x), "r"(bv.y))
            MMA_(d[0][0], a0, b0);
            MMA_(d[0][1], a0, b1);
            MMA_(d[1][0], a1, b0);
            MMA_(d[1][1], a1, b1);
#undef MMA_
        }
        __syncthreads();
    }

    int r = lane >> 2, c = lane & 3;
    int c2 = c * 2;
#pragma unroll
    for (int g = 0; g < 2; g++) {
        int n = bx * 64 + (n_sel * 2 + g) * 8 + c2;
        float2 bias = *(const float2*)(b3 + n);
#pragma unroll
        for (int f = 0; f < 2; f++) {
            int mb = by * 64 + (m_sel * 2 + f) * 16;
            float2 o0, o1;
            o0.x = d[f][g][0] + bias.x;
            o0.y = d[f][g][1] + bias.y;
            o1.x = d[f][g][2] + bias.x;
            o1.y = d[f][g][3] + bias.y;
            *(float2*)(out + (size_t)(mb + r) * D_ + n) = o0;
            *(float2*)(out + (size_t)(mb + r + 8) * D_ + n) = o1;
        }
    }
}

extern "C" void kernel_launch(void* const* d_in, const int* in_sizes, int n_in,
                              void* d_out, int out_size) {
    const float* x  = (const float*)d_in[0];   // [32,32,512]
    const float* xs = (const float*)d_in[1];   // [32,196,512]
    const float* W1 = (const float*)d_in[3];   // [512,512]
    const float* W3 = (const float*)d_in[5];   // [1024,512]
    const float* b3 = (const float*)d_in[7];   // [512]
    const float* V  = (const float*)d_in[8];   // [512,1]
    float* out = (float*)d_out;                // [32,32,512]

    prep_fused<<<256, 256>>>(x, W3, W1, V);
    scores_kernel<<<dim3(LCH, B_), 256>>>(xs);
    ctx_fused<<<dim3(LCH, B_), 128>>>(xs);
    gemm_tc<<<dim3(8, 16), 256>>>(b3, out);
}